// round 17
// baseline (speedup 1.0000x reference)
#include <cuda_runtime.h>
#include <math.h>

#define B_  32
#define H_  56
#define W_  56
#define C_  256
#define NROWS (B_ * H_)          // 1792
#define ROW_F4 (W_ * C_ / 4)     // 3584 float4 per row
#define GRID_  (NROWS / 2)       // 896 -> exactly one wave, 2 rows per CTA

// Cross-CTA handshake. Flags are monotonic publish-counters: after launch n,
// every flag == n. A CTA reads its OWN first-row flag to learn the epoch
// (race-free: only it writes that slot), publishes E+1, waits for >= E+1.
__device__ float2 g_pooled[NROWS * W_];
__device__ int    g_flag[NROWS];     // zero-initialized

__global__ __launch_bounds__(256) void fused_kernel(
    const float* __restrict__ x,
    const float* __restrict__ conv_w,   // [7][7][2] HWIO
    const float* __restrict__ conv_b,   // [1]
    float* __restrict__ out)
{
    __shared__ float2 pool7[7 * W_];
    __shared__ float  s_attn[W_];
    __shared__ float  s_w[98];

    const int tid  = threadIdx.x;
    const int warp = tid >> 5;
    const int lane = tid & 31;

    if (tid < 98) s_w[tid] = conv_w[tid];

    // Epoch from our own row-A flag (only this CTA ever writes it).
    const int E = *(volatile int*)&g_flag[blockIdx.x];

    // =====================================================================
    // Half 1: pool BOTH rows (x's only DRAM read), publish each.
    // All CTAs finish this half before any conv needs the flags.
    // =====================================================================
    #pragma unroll
    for (int rr = 0; rr < 2; rr++) {
        const int bh = blockIdx.x + rr * GRID_;
        const float4* __restrict__ x4 =
            reinterpret_cast<const float4*>(x) + (size_t)bh * ROW_F4;

        #pragma unroll
        for (int i = 0; i < 7; i++) {
            const int p = warp + 8 * i;            // 0..55
            const float4 a  = x4[p * 64 + lane];
            const float4 bv = x4[p * 64 + 32 + lane];
            float s = a.x + a.y + a.z + a.w + bv.x + bv.y + bv.z + bv.w;
            float m = fmaxf(fmaxf(fmaxf(a.x, a.y), fmaxf(a.z, a.w)),
                            fmaxf(fmaxf(bv.x, bv.y), fmaxf(bv.z, bv.w)));
            #pragma unroll
            for (int off = 16; off > 0; off >>= 1) {
                s += __shfl_xor_sync(0xffffffffu, s, off);
                m  = fmaxf(m, __shfl_xor_sync(0xffffffffu, m, off));
            }
            if (lane == 0) {
                g_pooled[bh * W_ + p] = make_float2(s * (1.0f / C_), m);
            }
        }
        __threadfence();                            // pooled row visible
        __syncthreads();
        if (tid == 0) atomicExch(&g_flag[bh], E + 1);   // release-publish
        __syncthreads();
    }

    // =====================================================================
    // Half 2: per row — wait (normally pre-satisfied), conv+sigmoid, scale.
    // x read #2 hits L2: all 103 MB of x is resident (L2=126MB) and the
    // __stcs out-stream doesn't evict it.
    // =====================================================================
    #pragma unroll
    for (int rr = 0; rr < 2; rr++) {
        const int bh = blockIdx.x + rr * GRID_;
        const int b  = bh / H_;
        const int h  = bh % H_;
        const size_t row_base4 = (size_t)bh * ROW_F4;
        const float4* __restrict__ x4 =
            reinterpret_cast<const float4*>(x) + row_base4;

        // Wait for neighbor rows (h-3..h+3, same image).
        if (tid < 7) {
            const int r = h + tid - 3;
            if (r >= 0 && r < H_) {
                volatile int* fp = &g_flag[b * H_ + r];
                while (*fp <= E) { __nanosleep(32); }
                __threadfence();                    // acquire
            }
        }
        __syncthreads();

        // Gather 7x56 pooled halo (tiny, L2-hot).
        for (int i = tid; i < 7 * W_; i += 256) {
            const int kr  = i / W_;
            const int col = i - kr * W_;
            const int row = h + kr - 3;
            float2 pv = make_float2(0.0f, 0.0f);
            if (row >= 0 && row < H_) pv = g_pooled[(b * H_ + row) * W_ + col];
            pool7[kr * W_ + col] = pv;
        }
        __syncthreads();

        // 7x7 conv (2->1) + sigmoid.
        if (tid < W_) {
            float acc = conv_b[0];
            #pragma unroll
            for (int kh = 0; kh < 7; kh++) {
                const int row = h + kh - 3;
                if (row < 0 || row >= H_) continue;
                #pragma unroll
                for (int kw = 0; kw < 7; kw++) {
                    const int col = tid + kw - 3;
                    if (col < 0 || col >= W_) continue;
                    const float2 pv = pool7[kh * W_ + col];
                    acc = fmaf(pv.x, s_w[(kh * 7 + kw) * 2],     acc);
                    acc = fmaf(pv.y, s_w[(kh * 7 + kw) * 2 + 1], acc);
                }
            }
            s_attn[tid] = 1.0f / (1.0f + expf(-acc));
        }
        __syncthreads();

        // Scale: read #2 (L2 hit) * attn -> streaming store.
        float4* __restrict__ o4 = reinterpret_cast<float4*>(out) + row_base4;
        #pragma unroll
        for (int it = 0; it < 14; it++) {
            const int idx = it * 256 + tid;
            const float a = s_attn[idx >> 6];
            float4 v = x4[idx];
            v.x *= a; v.y *= a; v.z *= a; v.w *= a;
            __stcs(&o4[idx], v);
        }
        __syncthreads();   // protect pool7/s_attn before next row
    }
}

extern "C" void kernel_launch(void* const* d_in, const int* in_sizes, int n_in,
                              void* d_out, int out_size) {
    const float* x      = (const float*)d_in[0];
    const float* conv_w = (const float*)d_in[1];
    const float* conv_b = (const float*)d_in[2];
    float* out          = (float*)d_out;

    fused_kernel<<<GRID_, 256>>>(x, conv_w, conv_b, out);
}